// round 16
// baseline (speedup 1.0000x reference)
#include <cuda_runtime.h>
#include <cstdint>

// Problem constants
#define NB      4
#define NN      2048
#define PP      2096128            // NN*(NN-1)/2
#define TOTALF  (NB*PP)            // 8384512 flat pair slots per output row
#define RPG     8                  // rows per group (ordering/compaction unit)
#define SPB     256                // groups per batch
#define NGRP    (NB * SPB)         // 1024 groups
#define CPGRP   (RPG * 64)         // 512 chunk slots per group
#define CBLK    512                // count blocks (each = 2 folded groups)
#define THREADS 256
#define FULL    0xffffffffu
#define NPAD    2080               // points + sentinel pad (covers j <= 2078)

// d2 <= 25.0f + 1ulp  <=>  sqrtf(d2) <= 5.0f (correctly rounded sqrt)
#define THR_BITS 0x41C80001u
#define NEG1F    0xBF800000        // -1.0f bits

#define FILLB   2048               // fill blocks inside combo kernel

// Scratch (__device__ globals; no allocations allowed)
__device__ unsigned g_mask[NGRP * CPGRP];   // 2 MB chunk validity bitmasks (per group)
__device__ int      g_soff[NGRP * CPGRP];   // 2 MB intra-group chunk offsets
__device__ int      g_gcnt[NGRP];
__device__ int      g_goff[NGRP];
__device__ int      g_total;

// ---------------------------------------------------------------------------
// K1: count — SoA smem (1 crossbar wavefront per LDS), folded group pair
// (s, 255-s) per block, sentinel pad, triangular ballots, 1024-chunk scan.
// ---------------------------------------------------------------------------
__global__ void __launch_bounds__(THREADS) count_kernel(const float* __restrict__ x) {
    __shared__ float sx[NPAD];
    __shared__ float sy[NPAD];
    __shared__ float sz[NPAD];
    __shared__ unsigned smask[2 * CPGRP];   // [0,512)=lo group, [512,1024)=hi
    __shared__ int wtot[8];
    __shared__ int wexc[8];
    __shared__ int s_cntlo;
    __shared__ int s_tot;

    const int k  = blockIdx.x;
    const int b  = k >> 7;                  // batch
    const int f  = k & 127;                 // fold index
    const int s_lo = f;
    const int s_hi = 255 - f;
    const int t  = threadIdx.x;
    const int w  = t >> 5;
    const int lane = t & 31;
    const float* xb = x + (size_t)b * NN * 3;

    // stage into SoA: explicit component split, no div/mod
    #pragma unroll
    for (int it = 0; it < 8; it++) {
        const int p = it * THREADS + t;
        const float* q = xb + 3 * p;
        sx[p] = q[0]; sy[p] = q[1]; sz[p] = q[2];
    }
    if (t < NPAD - NN) { sx[NN + t] = 1e30f; sy[NN + t] = 1e30f; sz[NN + t] = 1e30f; }
    #pragma unroll
    for (int s4 = 0; s4 < 4; s4++) smask[4 * t + s4] = 0;
    __syncthreads();

    const float thr = __uint_as_float(THR_BITS);
    #pragma unroll
    for (int h = 0; h < 2; h++) {
        const int r0 = (h ? s_hi : s_lo) * RPG;
        #pragma unroll
        for (int r = 0; r < RPG; r++) {
            const int i = r0 + r;
            const float xi = sx[i], yi = sy[i], zi = sz[i];
            const int nch = (NN - 1 - i + 31) >> 5;     // active chunks this row
            for (int c = w; c < nch; c += 8) {
                const int jj = i + 1 + (c << 5) + lane;
                float dx = __fsub_rn(xi, sx[jj]);
                float dy = __fsub_rn(yi, sy[jj]);
                float dz = __fsub_rn(zi, sz[jj]);
                float d2 = __fadd_rn(__fadd_rn(__fmul_rn(dx, dx), __fmul_rn(dy, dy)),
                                     __fmul_rn(dz, dz));
                unsigned m = __ballot_sync(FULL, d2 <= thr);
                if (lane == 0) smask[(h << 9) + (r << 6) + c] = m;
            }
        }
    }
    __syncthreads();

    // block scan over 1024 chunk popcounts (4 per thread, shfl-based)
    const uint4 mv = reinterpret_cast<const uint4*>(smask)[t];
    const int pc0 = __popc(mv.x), pc1 = __popc(mv.y);
    const int pc2 = __popc(mv.z), pc3 = __popc(mv.w);
    const int p = pc0 + pc1 + pc2 + pc3;
    int inc = p;
    #pragma unroll
    for (int d = 1; d < 32; d <<= 1) {
        int v = __shfl_up_sync(FULL, inc, d);
        if (lane >= d) inc += v;
    }
    if (lane == 31) wtot[w] = inc;
    __syncthreads();
    if (t < 32) {
        int vw = (lane < 8) ? wtot[lane] : 0;
        int winc = vw;
        #pragma unroll
        for (int d = 1; d < 8; d <<= 1) {
            int v = __shfl_up_sync(FULL, winc, d);
            if (lane >= d) winc += v;
        }
        if (lane < 8) wexc[lane] = winc - vw;
        if (lane == 7) s_tot = winc;
    }
    __syncthreads();
    const int e0 = wexc[w] + (inc - p);
    if (t == 128) s_cntlo = e0;     // exclusive prefix at chunk 512 = lo-group count
    __syncthreads();

    const int cnt_lo = s_cntlo;
    const int gi_lo = b * SPB + s_lo;
    const int gi_hi = b * SPB + s_hi;
    if (t == 0) {
        g_gcnt[gi_lo] = cnt_lo;
        g_gcnt[gi_hi] = s_tot - cnt_lo;
    }

    // dump per-group masks + intra-group offsets (hi rebased by cnt_lo)
    const int gi   = (t < 128) ? gi_lo : gi_hi;
    const int rb   = (t < 128) ? 0 : cnt_lo;
    const int slot = (4 * t) & 511;         // chunk index within group
    reinterpret_cast<uint4*>(&g_mask[gi * CPGRP + slot])[0] = mv;
    int4 ov;
    ov.x = e0 - rb; ov.y = ov.x + pc0; ov.z = ov.y + pc1; ov.w = ov.z + pc2;
    reinterpret_cast<int4*>(&g_soff[gi * CPGRP + slot])[0] = ov;
}

// ---------------------------------------------------------------------------
// K2: exclusive scan of 1024 group counts — one block, shfl-based
// ---------------------------------------------------------------------------
__global__ void __launch_bounds__(1024) scan_kernel() {
    __shared__ int wsum[32];
    const int t = threadIdx.x;
    const int w = t >> 5;
    const int lane = t & 31;

    int c = g_gcnt[t];
    int inc = c;
    #pragma unroll
    for (int d = 1; d < 32; d <<= 1) {
        int v = __shfl_up_sync(FULL, inc, d);
        if (lane >= d) inc += v;
    }
    if (lane == 31) wsum[w] = inc;
    __syncthreads();
    if (t < 32) {
        int vw = wsum[lane];
        int winc = vw;
        #pragma unroll
        for (int d = 1; d < 32; d <<= 1) {
            int v = __shfl_up_sync(FULL, winc, d);
            if (lane >= d) winc += v;
        }
        wsum[lane] = winc - vw;
    }
    __syncthreads();
    g_goff[t] = wsum[w] + inc - c;
    if (t == 1023) g_total = wsum[w] + inc;
}

// ---------------------------------------------------------------------------
// K3: combo — fill blocks write -1.0f over the invalid tail [total, TOTALF)
// of both rows; scatter blocks (one per group) write edges in [0, total).
// ---------------------------------------------------------------------------
__global__ void __launch_bounds__(256) combo_kernel(float* __restrict__ out) {
    const int t = threadIdx.x;

    if (blockIdx.x < FILLB) {
        // ---- fill role: grid-stride over int4 vectors, tail only
        const int total = g_total;
        const int NV = 2 * TOTALF / 4;       // TOTALF % 4 == 0: no row straddle
        int4 mm; mm.x = mm.y = mm.z = mm.w = NEG1F;
        int v = blockIdx.x * 256 + t;
        #pragma unroll
        for (int it = 0; it < 8; it++) {
            if (v < NV) {
                const int q0 = v * 4;
                const int local = (q0 < TOTALF) ? q0 : q0 - TOTALF;
                if (local >= total) {
                    reinterpret_cast<int4*>(out)[v] = mm;
                } else if (local + 4 > total) {
                    #pragma unroll
                    for (int e = 0; e < 4; e++)
                        if (local + e >= total) out[q0 + e] = -1.0f;
                }
            }
            v += FILLB * 256;
        }
        return;
    }

    // ---- scatter role: one block per group; uint2 wide loads, local bit-iter
    const int gi = blockIdx.x - FILLB;
    const int b  = gi >> 8;
    const int r0 = (gi & 255) * RPG;
    const int base = g_goff[gi];
    const int bofs = b * NN;
    float* out0 = out;
    float* out1 = out + TOTALF;

    const uint2 mm2 = *reinterpret_cast<const uint2*>(&g_mask[gi * CPGRP + 2 * t]);
    const int2  oo2 = *reinterpret_cast<const int2*>(&g_soff[gi * CPGRP + 2 * t]);

    #pragma unroll
    for (int s = 0; s < 2; s++) {
        unsigned m = s ? mm2.y : mm2.x;
        if (!m) continue;
        int off = base + (s ? oo2.y : oo2.x);
        const int ch = 2 * t + s;
        const int r = ch >> 6;               // row within group
        const int c = ch & 63;               // j-chunk
        const int i = r0 + r;
        const float fi = (float)(bofs + i);
        const int jb = bofs + i + 1 + (c << 5);
        while (m) {
            int bit = __ffs(m) - 1;
            m &= m - 1;
            out0[off] = fi;
            out1[off] = (float)(jb + bit);
            off++;
        }
    }
}

extern "C" void kernel_launch(void* const* d_in, const int* in_sizes, int n_in,
                              void* d_out, int out_size) {
    const float* x = (const float*)d_in[0];
    float* out = (float*)d_out;
    (void)in_sizes; (void)n_in; (void)out_size;

    count_kernel<<<CBLK, THREADS>>>(x);
    scan_kernel<<<1, 1024>>>();
    combo_kernel<<<FILLB + NGRP, 256>>>(out);
}